// round 13
// baseline (speedup 1.0000x reference)
#include <cuda_runtime.h>
#include <cuda_bf16.h>
#include <cstdint>

#define B_   4
#define C_   2048
#define HW_  196
#define M_   784          // B_*HW_
#define MPAD 896
#define NCLS 80
#define WD   300
#define ID   1024

// ---------------- scratch (static device globals; no allocs) ----------------
__device__ float g_v[ID];                   // fc4_w @ fc3_w
__device__ float g_wordp[NCLS * ID];        // word_features @ fc2_w^T
__device__ float g_imgpA[M_ * ID];          // x @ fc1_w^T  (K-split half 0)
__device__ float g_imgpB[M_ * ID];          // K-split half 1
__device__ float g_logits[B_ * NCLS * HW_]; // raw logits [b][n][hw]
// bf16 hi/lo splits, K-major rows of 2048 (16B-aligned for cp.async)
__device__ __align__(16) unsigned short g_ahi[MPAD * C_];
__device__ __align__(16) unsigned short g_alo[MPAD * C_];
__device__ __align__(16) unsigned short g_bhi[ID * C_];
__device__ __align__(16) unsigned short g_blo[ID * C_];

__device__ __forceinline__ uint32_t smem_u32(const void* p) {
    return (uint32_t)__cvta_generic_to_shared(p);
}

// ---------------- K_prep: fused split_a | split_b | v | wordp ----------------
#define PREP_BLOCKS 3648

__global__ void __launch_bounds__(256) k_prep(const float* __restrict__ img,
                                              const float* __restrict__ wf,
                                              const float* __restrict__ fc1w,
                                              const float* __restrict__ fc2w,
                                              const float* __restrict__ fc3w,
                                              const float* __restrict__ fc4w) {
    __shared__ float s[32 * 197];   // 25.2KB union
    int bx = blockIdx.x;
    int tid = threadIdx.x;

    if (bx < 256) {
        // ---- split_a ----
        int b = bx >> 6, c0 = (bx & 63) * 32;
        for (int e = tid; e < 32 * HW_; e += 256) {
            int ci = e / HW_, hw = e - ci * HW_;
            s[ci * 197 + hw] = img[((long)b * C_ + c0 + ci) * HW_ + hw];
        }
        __syncthreads();
        int ci = tid & 31, hw0 = tid >> 5;
        for (int hw = hw0; hw < HW_; hw += 8) {
            float x = s[ci * 197 + hw];
            __nv_bfloat16 h = __float2bfloat16_rn(x);
            __nv_bfloat16 l = __float2bfloat16_rn(x - __bfloat162float(h));
            long o = (long)(b * HW_ + hw) * C_ + c0 + ci;
            g_ahi[o] = __bfloat16_as_ushort(h);
            g_alo[o] = __bfloat16_as_ushort(l);
        }
    } else if (bx < 2304) {
        // ---- split_b ----
        int idx = (bx - 256) * 256 + tid;    // float4 index
        float4 v = ((const float4*)fc1w)[idx];
        float vv[4] = {v.x, v.y, v.z, v.w};
        unsigned h[4], l[4];
#pragma unroll
        for (int i = 0; i < 4; i++) {
            __nv_bfloat16 hh = __float2bfloat16_rn(vv[i]);
            __nv_bfloat16 ll = __float2bfloat16_rn(vv[i] - __bfloat162float(hh));
            h[i] = __bfloat16_as_ushort(hh);
            l[i] = __bfloat16_as_ushort(ll);
        }
        ((uint2*)g_bhi)[idx] = make_uint2(h[0] | (h[1] << 16), h[2] | (h[3] << 16));
        ((uint2*)g_blo)[idx] = make_uint2(l[0] | (l[1] << 16), l[2] | (l[3] << 16));
    } else if (bx < 2368) {
        // ---- v ----
        int d0 = (bx - 2304) * 16;
        int dl = tid & 15, eg = tid >> 4;
        int d  = d0 + dl;
        float acc = 0.f;
        int e0 = eg * 64;
#pragma unroll 8
        for (int e = e0; e < e0 + 64; e++)
            acc = fmaf(fc4w[e], fc3w[e * ID + d], acc);
        s[tid] = acc;
        __syncthreads();
        if (tid < 16) {
            float sum = 0.f;
#pragma unroll
            for (int g = 0; g < 16; g++) sum += s[g * 16 + tid];
            g_v[d0 + tid] = sum;
        }
    } else {
        // ---- wordp: d-tile (8 rows of fc2w in smem) x n-group (8 n), warp-per-n
        int idx = bx - 2368;           // 0..1279
        int d0 = (idx & 127) * 8;
        int n  = (idx >> 7) * 8 + (tid >> 5);
        for (int e = tid; e < 8 * WD; e += 256) {
            int i = e / WD, k = e - i * WD;
            s[e] = fc2w[(long)(d0 + i) * WD + k];
        }
        __syncthreads();
        int lane = tid & 31;
        float acc[8] = {0, 0, 0, 0, 0, 0, 0, 0};
        const float* wrow = wf + n * WD;
        for (int k = lane; k < WD; k += 32) {
            float wv = wrow[k];
#pragma unroll
            for (int i = 0; i < 8; i++) acc[i] = fmaf(wv, s[i * WD + k], acc[i]);
        }
#pragma unroll
        for (int i = 0; i < 8; i++) {
#pragma unroll
            for (int off = 16; off; off >>= 1)
                acc[i] += __shfl_xor_sync(~0u, acc[i], off);
        }
        if (lane == 0) {
#pragma unroll
            for (int i = 0; i < 8; i++) g_wordp[n * ID + d0 + i] = acc[i];
        }
    }
}

// ---------------- K_mma: bf16 mma.sync, 128Mx64N tiles, 224 CTAs, 2 CTA/SM ----
// stage = Ahi[128x64B]=8KB | Alo 8KB | Bhi[64x64B]=4KB | Blo 4KB = 24KB; 4 stages
#define AHI_OFF 0
#define ALO_OFF 8192
#define BHI_OFF 16384
#define BLO_OFF 20480
#define STAGE_BYTES 24576
#define MMA_SMEM    (4 * STAGE_BYTES)   // 96KB dynamic -> 2 CTAs/SM
#define NCHUNK 32                       // K=1024 per CTA z-half, chunks of 32

__device__ __forceinline__ void cp16(uint32_t s, const void* g) {
    asm volatile("cp.async.cg.shared.global [%0], [%1], 16;" :: "r"(s), "l"(g));
}
__device__ __forceinline__ void ldm4(uint32_t* r, uint32_t a) {
    asm volatile("ldmatrix.sync.aligned.m8n8.x4.shared.b16 {%0,%1,%2,%3}, [%4];"
                 : "=r"(r[0]), "=r"(r[1]), "=r"(r[2]), "=r"(r[3]) : "r"(a));
}
__device__ __forceinline__ void mma16816(float* c, const uint32_t* a, uint32_t b0, uint32_t b1) {
    asm volatile("mma.sync.aligned.m16n8k16.row.col.f32.bf16.bf16.f32 "
                 "{%0,%1,%2,%3}, {%4,%5,%6,%7}, {%8,%9}, {%0,%1,%2,%3};"
                 : "+f"(c[0]), "+f"(c[1]), "+f"(c[2]), "+f"(c[3])
                 : "r"(a[0]), "r"(a[1]), "r"(a[2]), "r"(a[3]), "r"(b0), "r"(b1));
}
#define SWZ64(row, ch) ((uint32_t)((row) * 64 + (((ch) ^ (((row) >> 1) & 3)) << 4)))

__global__ void __launch_bounds__(256, 2) k_mma() {
    extern __shared__ __align__(128) char smem[];
    uint32_t sbase = smem_u32(smem);
    int tid = threadIdx.x;
    int lane = tid & 31, wid = tid >> 5;
    int warp_m = wid >> 1, warp_n = wid & 1;        // 4 x 2 warps, warp 32M x 32N
    int m0 = blockIdx.y * 128, n0 = blockIdx.x * 64;
    long kz = (long)blockIdx.z * 1024;

    // loader: per thread 6 cp16 — A rows lr,lr+64 (x2 arrays), B row lr (x2 arrays)
    int lr = tid >> 2, c = tid & 3;
    uint32_t soff  = SWZ64(lr, c);
    uint32_t soff2 = SWZ64(lr + 64, c);
    long aGr  = (long)(m0 + lr) * C_ + kz + c * 8;
    long aGr2 = aGr + (long)64 * C_;
    long bGr  = (long)(n0 + lr) * C_ + kz + c * 8;

    auto load_stage = [&](int ci, int st) {
        uint32_t sa = sbase + (uint32_t)st * STAGE_BYTES;
        long ko = (long)ci * 32;
        cp16(sa + AHI_OFF + soff,  g_ahi + aGr  + ko);
        cp16(sa + AHI_OFF + soff2, g_ahi + aGr2 + ko);
        cp16(sa + ALO_OFF + soff,  g_alo + aGr  + ko);
        cp16(sa + ALO_OFF + soff2, g_alo + aGr2 + ko);
        cp16(sa + BHI_OFF + soff,  g_bhi + bGr  + ko);
        cp16(sa + BLO_OFF + soff,  g_blo + bGr  + ko);
        asm volatile("cp.async.commit_group;" ::: "memory");
    };

    int sel = lane >> 4;
    uint32_t a_off[2][2], b_off[2][2];
#pragma unroll
    for (int mt = 0; mt < 2; mt++) {
        int row = warp_m * 32 + mt * 16 + (lane & 15);
#pragma unroll
        for (int ks = 0; ks < 2; ks++)
            a_off[mt][ks] = SWZ64(row, 2 * ks + sel);
    }
#pragma unroll
    for (int bt = 0; bt < 2; bt++) {
        int row = warp_n * 32 + bt * 16 + (lane & 15);
#pragma unroll
        for (int ks = 0; ks < 2; ks++)
            b_off[bt][ks] = SWZ64(row, 2 * ks + sel);
    }

    float acc[2][4][4];
#pragma unroll
    for (int i = 0; i < 2; i++)
#pragma unroll
        for (int j = 0; j < 4; j++)
#pragma unroll
            for (int q = 0; q < 4; q++) acc[i][j][q] = 0.f;

    load_stage(0, 0);
    load_stage(1, 1);
    load_stage(2, 2);

    for (int ci = 0; ci < NCHUNK; ci++) {
        asm volatile("cp.async.wait_group 2;" ::: "memory");
        __syncthreads();
        if (ci + 3 < NCHUNK) load_stage(ci + 3, (ci + 3) & 3);
        else asm volatile("cp.async.commit_group;" ::: "memory");

        uint32_t sa = sbase + (uint32_t)(ci & 3) * STAGE_BYTES;
#pragma unroll
        for (int ks = 0; ks < 2; ks++) {
            uint32_t ahi[2][4], alo[2][4], bhi[2][4], blo[2][4];
#pragma unroll
            for (int mt = 0; mt < 2; mt++) {
                ldm4(ahi[mt], sa + AHI_OFF + a_off[mt][ks]);
                ldm4(alo[mt], sa + ALO_OFF + a_off[mt][ks]);
            }
#pragma unroll
            for (int bt = 0; bt < 2; bt++) {
                ldm4(bhi[bt], sa + BHI_OFF + b_off[bt][ks]);
                ldm4(blo[bt], sa + BLO_OFF + b_off[bt][ks]);
            }
#pragma unroll
            for (int mt = 0; mt < 2; mt++) {
#pragma unroll
                for (int bt = 0; bt < 2; bt++) {
                    mma16816(acc[mt][2 * bt],     ahi[mt], bhi[bt][0], bhi[bt][2]);
                    mma16816(acc[mt][2 * bt + 1], ahi[mt], bhi[bt][1], bhi[bt][3]);
                    mma16816(acc[mt][2 * bt],     ahi[mt], blo[bt][0], blo[bt][2]);
                    mma16816(acc[mt][2 * bt + 1], ahi[mt], blo[bt][1], blo[bt][3]);
                    mma16816(acc[mt][2 * bt],     alo[mt], bhi[bt][0], bhi[bt][2]);
                    mma16816(acc[mt][2 * bt + 1], alo[mt], bhi[bt][1], bhi[bt][3]);
                }
            }
        }
    }

    float* outb = blockIdx.z ? g_imgpB : g_imgpA;
#pragma unroll
    for (int mt = 0; mt < 2; mt++) {
#pragma unroll
        for (int nt = 0; nt < 4; nt++) {
            int prow = m0 + warp_m * 32 + mt * 16 + (lane >> 2);
            int ncol = n0 + warp_n * 32 + nt * 8 + (lane & 3) * 2;
            if (prow < M_)
                *(float2*)(outb + (long)prow * ID + ncol) =
                    make_float2(acc[mt][nt][0], acc[mt][nt][1]);
            if (prow + 8 < M_)
                *(float2*)(outb + (long)(prow + 8) * ID + ncol) =
                    make_float2(acc[mt][nt][2], acc[mt][nt][3]);
        }
    }
}

// ---------------- K_logits: 4 pixels x 40 classes per block (392 blocks) ----------------
__global__ void __launch_bounds__(256) k_logits() {
    __shared__ float s_img[4 * ID];
    __shared__ float s_v[ID];
    int p0 = (blockIdx.x >> 1) * 4;
    int n0 = (blockIdx.x & 1) * 40;
    for (int e = threadIdx.x; e < 4 * ID; e += 256) {
        long o = (long)p0 * ID + e;
        s_img[e] = g_imgpA[o] + g_imgpB[o];
    }
    for (int e = threadIdx.x; e < ID; e += 256) s_v[e] = g_v[e];
    __syncthreads();
    int w = threadIdx.x >> 5, lane = threadIdx.x & 31;
    int b = p0 / HW_;                  // 4 | 196 so no straddle
    int hw0 = p0 - b * HW_;
    for (int n = n0 + w; n < n0 + 40; n += 8) {
        const float* wrow = g_wordp + n * ID;
        float a0 = 0.f, a1 = 0.f, a2 = 0.f, a3 = 0.f;
#pragma unroll 4
        for (int d = lane; d < ID; d += 32) {
            float wv = wrow[d];
            float vv = s_v[d];
            float t0, t1, t2, t3;
            float x0 = s_img[d] * wv;
            float x1 = s_img[ID + d] * wv;
            float x2 = s_img[2 * ID + d] * wv;
            float x3 = s_img[3 * ID + d] * wv;
            asm("tanh.approx.f32 %0, %1;" : "=f"(t0) : "f"(x0));
            asm("tanh.approx.f32 %0, %1;" : "=f"(t1) : "f"(x1));
            asm("tanh.approx.f32 %0, %1;" : "=f"(t2) : "f"(x2));
            asm("tanh.approx.f32 %0, %1;" : "=f"(t3) : "f"(x3));
            a0 = fmaf(vv, t0, a0);
            a1 = fmaf(vv, t1, a1);
            a2 = fmaf(vv, t2, a2);
            a3 = fmaf(vv, t3, a3);
        }
#pragma unroll
        for (int off = 16; off; off >>= 1) {
            a0 += __shfl_xor_sync(~0u, a0, off);
            a1 += __shfl_xor_sync(~0u, a1, off);
            a2 += __shfl_xor_sync(~0u, a2, off);
            a3 += __shfl_xor_sync(~0u, a3, off);
        }
        if (lane == 0) {
            float* dst = g_logits + (b * NCLS + n) * HW_ + hw0;
            dst[0] = a0; dst[1] = a1; dst[2] = a2; dst[3] = a3;
        }
    }
}

// ---------------- K_pool: local softmax + out[b,n,c] = sum_hw coef * x ----------------
// dynamic smem: s_x[32][196] + s_c[80][196]; coef softmaxed IN SMEM (g_logits raw)
#define HW4 (HW_ / 4)                              // 49
#define POOL_SMEM ((32 * HW_ + NCLS * HW_) * 4)    // 87.8KB

__global__ void __launch_bounds__(256) k_pool(const float* __restrict__ img,
                                              float* __restrict__ out) {
    extern __shared__ __align__(16) float sp[];
    float* s_x = sp;                 // [32][196]
    float* s_c = sp + 32 * HW_;      // [80][196]
    int b  = blockIdx.y;
    int c0 = blockIdx.x * 32;
    int tid = threadIdx.x;

    const float4* imgB = (const float4*)(img + (long)b * C_ * HW_);
    float4* sx4 = (float4*)s_x;
    for (int e = tid; e < 32 * HW4; e += 256) {
        int cl = e / HW4, q = e - cl * HW4;
        sx4[e] = imgB[(long)(c0 + cl) * HW4 + q];
    }
    const float4* log4 = (const float4*)(g_logits + (long)b * NCLS * HW_);
    float4* sc4 = (float4*)s_c;
    for (int e = tid; e < NCLS * HW4; e += 256)
        sc4[e] = log4[e];
    __syncthreads();

    // local softmax over each of the 80 rows (warp w handles rows w, w+8, ...)
    {
        int w = tid >> 5, lane = tid & 31;
        for (int r = w; r < NCLS; r += 8) {
            float* row = s_c + r * HW_;
            float v[7];
            float mx = -1e30f;
#pragma unroll
            for (int i = 0; i < 7; i++) {
                int hw = lane + 32 * i;
                v[i] = (hw < HW_) ? row[hw] : -1e30f;
                mx = fmaxf(mx, v[i]);
            }
#pragma unroll
            for (int off = 16; off; off >>= 1)
                mx = fmaxf(mx, __shfl_xor_sync(~0u, mx, off));
            float sum = 0.f;
#pragma unroll
            for (int i = 0; i < 7; i++) {
                int hw = lane + 32 * i;
                float e = (hw < HW_) ? __expf(v[i] - mx) : 0.0f;
                v[i] = e;
                sum += e;
            }
#pragma unroll
            for (int off = 16; off; off >>= 1)
                sum += __shfl_xor_sync(~0u, sum, off);
            float inv = __fdividef(1.0f, sum);
#pragma unroll
            for (int i = 0; i < 7; i++) {
                int hw = lane + 32 * i;
                if (hw < HW_) row[hw] = v[i] * inv;
            }
        }
    }
    __syncthreads();

    int cl = tid & 31, np = tid >> 5;   // warp np handles n = np + 8j
    float acc[10];
#pragma unroll
    for (int j = 0; j < 10; j++) acc[j] = 0.f;

    const float4* x4 = (const float4*)(s_x + cl * HW_);
    for (int q = 0; q < HW4; q++) {
        float4 xv = x4[q];
#pragma unroll
        for (int j = 0; j < 10; j++) {
            float4 cv = *(const float4*)(s_c + (np + 8 * j) * HW_ + 4 * q);
            acc[j] = fmaf(xv.x, cv.x, acc[j]);
            acc[j] = fmaf(xv.y, cv.y, acc[j]);
            acc[j] = fmaf(xv.z, cv.z, acc[j]);
            acc[j] = fmaf(xv.w, cv.w, acc[j]);
        }
    }
#pragma unroll
    for (int j = 0; j < 10; j++) {
        int n = np + 8 * j;
        out[((long)b * NCLS + n) * C_ + c0 + cl] = acc[j];
    }
}

// ---------------- launch ----------------
extern "C" void kernel_launch(void* const* d_in, const int* in_sizes, int n_in,
                              void* d_out, int out_size) {
    (void)in_sizes; (void)n_in; (void)out_size;
    const float* img  = (const float*)d_in[0];  // [B,C,H,W]
    const float* wf   = (const float*)d_in[1];  // [N,WD]
    const float* fc1w = (const float*)d_in[2];  // [ID,C]
    const float* fc2w = (const float*)d_in[3];  // [ID,WD]
    const float* fc3w = (const float*)d_in[4];  // [ID,ID]
    // d_in[5] fc3_b, d_in[7] fc4_b: constant over softmax axis -> cancel
    const float* fc4w = (const float*)d_in[6];  // [1,ID]
    float* out = (float*)d_out;                 // [B,N,C] fp32

    cudaFuncSetAttribute(k_mma,  cudaFuncAttributeMaxDynamicSharedMemorySize, MMA_SMEM);
    cudaFuncSetAttribute(k_pool, cudaFuncAttributeMaxDynamicSharedMemorySize, POOL_SMEM);

    k_prep  <<<PREP_BLOCKS, 256>>>(img, wf, fc1w, fc2w, fc3w, fc4w);
    k_mma   <<<dim3(16, 7, 2), 256, MMA_SMEM>>>();
    k_logits<<<392, 256>>>();
    k_pool  <<<dim3(64, 4), 256, POOL_SMEM>>>(img, out);
}

// round 15
// speedup vs baseline: 1.0290x; 1.0290x over previous
#include <cuda_runtime.h>
#include <cuda_bf16.h>
#include <cstdint>

#define B_   4
#define C_   2048
#define HW_  196
#define M_   784          // B_*HW_
#define MPAD 896
#define NCLS 80
#define WD   300
#define ID   1024

// ---------------- scratch (static device globals; no allocs) ----------------
__device__ float g_v[ID];                   // fc4_w @ fc3_w
__device__ float g_wordp[NCLS * ID];        // word_features @ fc2_w^T
__device__ float g_imgpA[M_ * ID];          // x @ fc1_w^T  (K-split half 0)
__device__ float g_imgpB[M_ * ID];          // K-split half 1
__device__ float g_logits[B_ * NCLS * HW_]; // [b][n][hw], softmaxed in place
// bf16 hi/lo splits, K-major rows of 2048 (16B-aligned for cp.async)
__device__ __align__(16) unsigned short g_ahi[MPAD * C_];
__device__ __align__(16) unsigned short g_alo[MPAD * C_];
__device__ __align__(16) unsigned short g_bhi[ID * C_];
__device__ __align__(16) unsigned short g_blo[ID * C_];

__device__ __forceinline__ uint32_t smem_u32(const void* p) {
    return (uint32_t)__cvta_generic_to_shared(p);
}

// ---------------- K_prep: fused split_a | split_b | v | wordp ----------------
#define PREP_BLOCKS 3648

__global__ void __launch_bounds__(256) k_prep(const float* __restrict__ img,
                                              const float* __restrict__ wf,
                                              const float* __restrict__ fc1w,
                                              const float* __restrict__ fc2w,
                                              const float* __restrict__ fc3w,
                                              const float* __restrict__ fc4w) {
    __shared__ float s[32 * 197];   // 25.2KB union
    int bx = blockIdx.x;
    int tid = threadIdx.x;

    if (bx < 256) {
        // ---- split_a ----
        int b = bx >> 6, c0 = (bx & 63) * 32;
        for (int e = tid; e < 32 * HW_; e += 256) {
            int ci = e / HW_, hw = e - ci * HW_;
            s[ci * 197 + hw] = img[((long)b * C_ + c0 + ci) * HW_ + hw];
        }
        __syncthreads();
        int ci = tid & 31, hw0 = tid >> 5;
        for (int hw = hw0; hw < HW_; hw += 8) {
            float x = s[ci * 197 + hw];
            __nv_bfloat16 h = __float2bfloat16_rn(x);
            __nv_bfloat16 l = __float2bfloat16_rn(x - __bfloat162float(h));
            long o = (long)(b * HW_ + hw) * C_ + c0 + ci;
            g_ahi[o] = __bfloat16_as_ushort(h);
            g_alo[o] = __bfloat16_as_ushort(l);
        }
    } else if (bx < 2304) {
        // ---- split_b ----
        int idx = (bx - 256) * 256 + tid;    // float4 index
        float4 v = ((const float4*)fc1w)[idx];
        float vv[4] = {v.x, v.y, v.z, v.w};
        unsigned h[4], l[4];
#pragma unroll
        for (int i = 0; i < 4; i++) {
            __nv_bfloat16 hh = __float2bfloat16_rn(vv[i]);
            __nv_bfloat16 ll = __float2bfloat16_rn(vv[i] - __bfloat162float(hh));
            h[i] = __bfloat16_as_ushort(hh);
            l[i] = __bfloat16_as_ushort(ll);
        }
        ((uint2*)g_bhi)[idx] = make_uint2(h[0] | (h[1] << 16), h[2] | (h[3] << 16));
        ((uint2*)g_blo)[idx] = make_uint2(l[0] | (l[1] << 16), l[2] | (l[3] << 16));
    } else if (bx < 2368) {
        // ---- v ----
        int d0 = (bx - 2304) * 16;
        int dl = tid & 15, eg = tid >> 4;
        int d  = d0 + dl;
        float acc = 0.f;
        int e0 = eg * 64;
#pragma unroll 8
        for (int e = e0; e < e0 + 64; e++)
            acc = fmaf(fc4w[e], fc3w[e * ID + d], acc);
        s[tid] = acc;
        __syncthreads();
        if (tid < 16) {
            float sum = 0.f;
#pragma unroll
            for (int g = 0; g < 16; g++) sum += s[g * 16 + tid];
            g_v[d0 + tid] = sum;
        }
    } else {
        // ---- wordp: d-tile (8 rows of fc2w in smem) x n-group (8 n), warp-per-n
        int idx = bx - 2368;           // 0..1279
        int d0 = (idx & 127) * 8;
        int n  = (idx >> 7) * 8 + (tid >> 5);
        for (int e = tid; e < 8 * WD; e += 256) {
            int i = e / WD, k = e - i * WD;
            s[e] = fc2w[(long)(d0 + i) * WD + k];
        }
        __syncthreads();
        int lane = tid & 31;
        float acc[8] = {0, 0, 0, 0, 0, 0, 0, 0};
        const float* wrow = wf + n * WD;
        for (int k = lane; k < WD; k += 32) {
            float wv = wrow[k];
#pragma unroll
            for (int i = 0; i < 8; i++) acc[i] = fmaf(wv, s[i * WD + k], acc[i]);
        }
#pragma unroll
        for (int i = 0; i < 8; i++) {
#pragma unroll
            for (int off = 16; off; off >>= 1)
                acc[i] += __shfl_xor_sync(~0u, acc[i], off);
        }
        if (lane == 0) {
#pragma unroll
            for (int i = 0; i < 8; i++) g_wordp[n * ID + d0 + i] = acc[i];
        }
    }
}

// ---------------- K_mma: bf16 mma.sync, shared-tile 3-term, 128x128, K-split 2 ----
#define STAGE_BYTES 32768
#define MMA_SMEM    (4 * STAGE_BYTES)   // 128KB dynamic
#define NCHUNK 32                       // K=1024 per CTA z-half, chunks of 32

__device__ __forceinline__ void cp16(uint32_t s, const void* g) {
    asm volatile("cp.async.cg.shared.global [%0], [%1], 16;" :: "r"(s), "l"(g));
}
__device__ __forceinline__ void ldm4(uint32_t* r, uint32_t a) {
    asm volatile("ldmatrix.sync.aligned.m8n8.x4.shared.b16 {%0,%1,%2,%3}, [%4];"
                 : "=r"(r[0]), "=r"(r[1]), "=r"(r[2]), "=r"(r[3]) : "r"(a));
}
__device__ __forceinline__ void mma16816(float* c, const uint32_t* a, uint32_t b0, uint32_t b1) {
    asm volatile("mma.sync.aligned.m16n8k16.row.col.f32.bf16.bf16.f32 "
                 "{%0,%1,%2,%3}, {%4,%5,%6,%7}, {%8,%9}, {%0,%1,%2,%3};"
                 : "+f"(c[0]), "+f"(c[1]), "+f"(c[2]), "+f"(c[3])
                 : "r"(a[0]), "r"(a[1]), "r"(a[2]), "r"(a[3]), "r"(b0), "r"(b1));
}
#define SWZ64(row, ch) ((uint32_t)((row) * 64 + (((ch) ^ (((row) >> 1) & 3)) << 4)))

__global__ void __launch_bounds__(256) k_mma() {
    extern __shared__ __align__(128) char smem[];
    uint32_t sbase = smem_u32(smem);
    int tid = threadIdx.x;
    int lane = tid & 31, wid = tid >> 5;
    int warp_m = wid >> 1, warp_n = wid & 1;        // 4 x 2 warps, warp 32M x 64N
    int m0 = blockIdx.y * 128, n0 = blockIdx.x * 128;
    long kz = (long)blockIdx.z * 1024;

    int lr = tid >> 2, c = tid & 3;
    uint32_t soff  = SWZ64(lr, c);
    uint32_t soff2 = SWZ64(lr + 64, c);
    long aGr  = (long)(m0 + lr) * C_ + kz + c * 8;
    long aGr2 = aGr + (long)64 * C_;
    long bGr  = (long)(n0 + lr) * C_ + kz + c * 8;
    long bGr2 = bGr + (long)64 * C_;

    auto load_stage = [&](int ci, int st) {
        uint32_t sa = sbase + (uint32_t)st * STAGE_BYTES;
        long ko = (long)ci * 32;
        cp16(sa + soff,          g_ahi + aGr  + ko);
        cp16(sa + soff2,         g_ahi + aGr2 + ko);
        cp16(sa + 8192  + soff,  g_alo + aGr  + ko);
        cp16(sa + 8192  + soff2, g_alo + aGr2 + ko);
        cp16(sa + 16384 + soff,  g_bhi + bGr  + ko);
        cp16(sa + 16384 + soff2, g_bhi + bGr2 + ko);
        cp16(sa + 24576 + soff,  g_blo + bGr  + ko);
        cp16(sa + 24576 + soff2, g_blo + bGr2 + ko);
        asm volatile("cp.async.commit_group;" ::: "memory");
    };

    int sel = lane >> 4;
    uint32_t a_off[2][2], b_off[4][2];
#pragma unroll
    for (int mt = 0; mt < 2; mt++) {
        int row = warp_m * 32 + mt * 16 + (lane & 15);
#pragma unroll
        for (int ks = 0; ks < 2; ks++)
            a_off[mt][ks] = SWZ64(row, 2 * ks + sel);
    }
#pragma unroll
    for (int bt = 0; bt < 4; bt++) {
        int row = warp_n * 64 + bt * 16 + (lane & 15);
#pragma unroll
        for (int ks = 0; ks < 2; ks++)
            b_off[bt][ks] = SWZ64(row, 2 * ks + sel);
    }

    float acc[2][8][4];
#pragma unroll
    for (int i = 0; i < 2; i++)
#pragma unroll
        for (int j = 0; j < 8; j++)
#pragma unroll
            for (int q = 0; q < 4; q++) acc[i][j][q] = 0.f;

    load_stage(0, 0);
    load_stage(1, 1);
    load_stage(2, 2);

    for (int ci = 0; ci < NCHUNK; ci++) {
        asm volatile("cp.async.wait_group 2;" ::: "memory");
        __syncthreads();
        if (ci + 3 < NCHUNK) load_stage(ci + 3, (ci + 3) & 3);
        else asm volatile("cp.async.commit_group;" ::: "memory");

        uint32_t sa = sbase + (uint32_t)(ci & 3) * STAGE_BYTES;
#pragma unroll
        for (int ks = 0; ks < 2; ks++) {
            uint32_t ahi[2][4], alo[2][4], bhi[4][4], blo[4][4];
#pragma unroll
            for (int mt = 0; mt < 2; mt++) {
                ldm4(ahi[mt], sa + a_off[mt][ks]);
                ldm4(alo[mt], sa + 8192 + a_off[mt][ks]);
            }
#pragma unroll
            for (int bt = 0; bt < 4; bt++) {
                ldm4(bhi[bt], sa + 16384 + b_off[bt][ks]);
                ldm4(blo[bt], sa + 24576 + b_off[bt][ks]);
            }
#pragma unroll
            for (int mt = 0; mt < 2; mt++) {
#pragma unroll
                for (int bt = 0; bt < 4; bt++) {
                    mma16816(acc[mt][2 * bt],     ahi[mt], bhi[bt][0], bhi[bt][2]);
                    mma16816(acc[mt][2 * bt + 1], ahi[mt], bhi[bt][1], bhi[bt][3]);
                    mma16816(acc[mt][2 * bt],     ahi[mt], blo[bt][0], blo[bt][2]);
                    mma16816(acc[mt][2 * bt + 1], ahi[mt], blo[bt][1], blo[bt][3]);
                    mma16816(acc[mt][2 * bt],     alo[mt], bhi[bt][0], bhi[bt][2]);
                    mma16816(acc[mt][2 * bt + 1], alo[mt], bhi[bt][1], bhi[bt][3]);
                }
            }
        }
    }

    float* outb = blockIdx.z ? g_imgpB : g_imgpA;
#pragma unroll
    for (int mt = 0; mt < 2; mt++) {
#pragma unroll
        for (int nt = 0; nt < 8; nt++) {
            int prow = m0 + warp_m * 32 + mt * 16 + (lane >> 2);
            int ncol = n0 + warp_n * 64 + nt * 8 + (lane & 3) * 2;
            if (prow < M_)
                *(float2*)(outb + (long)prow * ID + ncol) =
                    make_float2(acc[mt][nt][0], acc[mt][nt][1]);
            if (prow + 8 < M_)
                *(float2*)(outb + (long)(prow + 8) * ID + ncol) =
                    make_float2(acc[mt][nt][2], acc[mt][nt][3]);
        }
    }
}

// ---------------- K_logits: 4 pixels x 40 classes per block (392 blocks) ----------------
__global__ void __launch_bounds__(256) k_logits() {
    __shared__ float s_img[4 * ID];
    __shared__ float s_v[ID];
    int p0 = (blockIdx.x >> 1) * 4;
    int n0 = (blockIdx.x & 1) * 40;
    for (int e = threadIdx.x; e < 4 * ID; e += 256) {
        long o = (long)p0 * ID + e;
        s_img[e] = g_imgpA[o] + g_imgpB[o];
    }
    for (int e = threadIdx.x; e < ID; e += 256) s_v[e] = g_v[e];
    __syncthreads();
    int w = threadIdx.x >> 5, lane = threadIdx.x & 31;
    int b = p0 / HW_;                  // 4 | 196 so no straddle
    int hw0 = p0 - b * HW_;
    for (int n = n0 + w; n < n0 + 40; n += 8) {
        const float* wrow = g_wordp + n * ID;
        float a0 = 0.f, a1 = 0.f, a2 = 0.f, a3 = 0.f;
#pragma unroll 4
        for (int d = lane; d < ID; d += 32) {
            float wv = wrow[d];
            float vv = s_v[d];
            float t0, t1, t2, t3;
            float x0 = s_img[d] * wv;
            float x1 = s_img[ID + d] * wv;
            float x2 = s_img[2 * ID + d] * wv;
            float x3 = s_img[3 * ID + d] * wv;
            asm("tanh.approx.f32 %0, %1;" : "=f"(t0) : "f"(x0));
            asm("tanh.approx.f32 %0, %1;" : "=f"(t1) : "f"(x1));
            asm("tanh.approx.f32 %0, %1;" : "=f"(t2) : "f"(x2));
            asm("tanh.approx.f32 %0, %1;" : "=f"(t3) : "f"(x3));
            a0 = fmaf(vv, t0, a0);
            a1 = fmaf(vv, t1, a1);
            a2 = fmaf(vv, t2, a2);
            a3 = fmaf(vv, t3, a3);
        }
#pragma unroll
        for (int off = 16; off; off >>= 1) {
            a0 += __shfl_xor_sync(~0u, a0, off);
            a1 += __shfl_xor_sync(~0u, a1, off);
            a2 += __shfl_xor_sync(~0u, a2, off);
            a3 += __shfl_xor_sync(~0u, a3, off);
        }
        if (lane == 0) {
            float* dst = g_logits + (b * NCLS + n) * HW_ + hw0;
            dst[0] = a0; dst[1] = a1; dst[2] = a2; dst[3] = a3;
        }
    }
}

// ---------------- K_softmax: warp-per-(b,n) row over 196 positions ----------------
__global__ void __launch_bounds__(256) k_softmax() {
    int row = blockIdx.x * 8 + (threadIdx.x >> 5);   // 40 blocks x 8 warps = 320 rows
    float* base = g_logits + row * HW_;
    int lane = threadIdx.x & 31;
    float v[7];
    float mx = -1e30f;
#pragma unroll
    for (int i = 0; i < 7; i++) {
        int hw = lane + 32 * i;
        v[i] = (hw < HW_) ? base[hw] : -1e30f;
        mx = fmaxf(mx, v[i]);
    }
#pragma unroll
    for (int off = 16; off; off >>= 1) mx = fmaxf(mx, __shfl_xor_sync(~0u, mx, off));
    float sum = 0.f;
#pragma unroll
    for (int i = 0; i < 7; i++) {
        int hw = lane + 32 * i;
        float e = (hw < HW_) ? __expf(v[i] - mx) : 0.0f;
        v[i] = e;
        sum += e;
    }
#pragma unroll
    for (int off = 16; off; off >>= 1) sum += __shfl_xor_sync(~0u, sum, off);
    float inv = __fdividef(1.0f, sum);
#pragma unroll
    for (int i = 0; i < 7; i++) {
        int hw = lane + 32 * i;
        if (hw < HW_) base[hw] = v[i] * inv;
    }
}

// ---------------- K_pool: out[b,n,c] = sum_hw coef[b,n,hw] * x[b,hw,c] ----------------
// split over n-halves: block = (32 c, 40 n, b); grid (64,2,4) = 512 blocks
// smem 55KB -> multiple CTAs/SM; float4 fills + float4 inner loop, 5 n-acc/thread
#define HW4 (HW_ / 4)                              // 49
#define POOL_SMEM ((32 * HW_ + 40 * HW_) * 4)      // 56448 B

__global__ void __launch_bounds__(256) k_pool(const float* __restrict__ img,
                                              float* __restrict__ out) {
    extern __shared__ __align__(16) float sp[];
    float* s_x = sp;                 // [32][196]
    float* s_c = sp + 32 * HW_;      // [40][196]
    int b  = blockIdx.z;
    int nh = blockIdx.y;             // n-half: classes [nh*40, nh*40+40)
    int c0 = blockIdx.x * 32;
    int tid = threadIdx.x;

    const float4* imgB = (const float4*)(img + (long)b * C_ * HW_);
    float4* sx4 = (float4*)s_x;
    for (int e = tid; e < 32 * HW4; e += 256) {
        int cl = e / HW4, q = e - cl * HW4;
        sx4[e] = imgB[(long)(c0 + cl) * HW4 + q];
    }
    const float4* log4 = (const float4*)(g_logits + ((long)b * NCLS + nh * 40) * HW_);
    float4* sc4 = (float4*)s_c;
    for (int e = tid; e < 40 * HW4; e += 256)
        sc4[e] = log4[e];
    __syncthreads();

    int cl = tid & 31, np = tid >> 5;   // warp np handles local n = np + 8j, j<5
    float acc[5];
#pragma unroll
    for (int j = 0; j < 5; j++) acc[j] = 0.f;

    const float4* x4 = (const float4*)(s_x + cl * HW_);
    for (int q = 0; q < HW4; q++) {
        float4 xv = x4[q];
#pragma unroll
        for (int j = 0; j < 5; j++) {
            float4 cv = *(const float4*)(s_c + (np + 8 * j) * HW_ + 4 * q);
            acc[j] = fmaf(xv.x, cv.x, acc[j]);
            acc[j] = fmaf(xv.y, cv.y, acc[j]);
            acc[j] = fmaf(xv.z, cv.z, acc[j]);
            acc[j] = fmaf(xv.w, cv.w, acc[j]);
        }
    }
#pragma unroll
    for (int j = 0; j < 5; j++) {
        int n = nh * 40 + np + 8 * j;
        out[((long)b * NCLS + n) * C_ + c0 + cl] = acc[j];
    }
}

// ---------------- launch ----------------
extern "C" void kernel_launch(void* const* d_in, const int* in_sizes, int n_in,
                              void* d_out, int out_size) {
    (void)in_sizes; (void)n_in; (void)out_size;
    const float* img  = (const float*)d_in[0];  // [B,C,H,W]
    const float* wf   = (const float*)d_in[1];  // [N,WD]
    const float* fc1w = (const float*)d_in[2];  // [ID,C]
    const float* fc2w = (const float*)d_in[3];  // [ID,WD]
    const float* fc3w = (const float*)d_in[4];  // [ID,ID]
    // d_in[5] fc3_b, d_in[7] fc4_b: constant over softmax axis -> cancel
    const float* fc4w = (const float*)d_in[6];  // [1,ID]
    float* out = (float*)d_out;                 // [B,N,C] fp32

    cudaFuncSetAttribute(k_mma,  cudaFuncAttributeMaxDynamicSharedMemorySize, MMA_SMEM);
    cudaFuncSetAttribute(k_pool, cudaFuncAttributeMaxDynamicSharedMemorySize, POOL_SMEM);

    k_prep   <<<PREP_BLOCKS, 256>>>(img, wf, fc1w, fc2w, fc3w, fc4w);
    k_mma    <<<dim3(8, 7, 2), 256, MMA_SMEM>>>();
    k_logits <<<392, 256>>>();
    k_softmax<<<40, 256>>>();
    k_pool   <<<dim3(64, 2, 4), 256, POOL_SMEM>>>(img, out);
}

// round 17
// speedup vs baseline: 1.1618x; 1.1291x over previous
#include <cuda_runtime.h>
#include <cuda_fp16.h>
#include <cstdint>

#define B_   4
#define C_   2048
#define HW_  196
#define M_   784          // B_*HW_
#define MPAD 896
#define NCLS 80
#define WD   300
#define ID   1024

// ---------------- scratch (static device globals; no allocs) ----------------
__device__ float g_v[ID];                   // fc4_w @ fc3_w
__device__ float g_wordp[NCLS * ID];        // word_features @ fc2_w^T
__device__ float g_imgpA[M_ * ID];          // x @ fc1_w^T  (K-split half 0)
__device__ float g_imgpB[M_ * ID];          // K-split half 1
__device__ float g_logits[B_ * NCLS * HW_]; // [b][n][hw], softmaxed in place
// fp16 A hi/lo split + fp16 B, K-major rows of 2048 (16B-aligned for cp.async)
__device__ __align__(16) unsigned short g_ahi[MPAD * C_];
__device__ __align__(16) unsigned short g_alo[MPAD * C_];
__device__ __align__(16) unsigned short g_bhi[ID * C_];

__device__ __forceinline__ uint32_t smem_u32(const void* p) {
    return (uint32_t)__cvta_generic_to_shared(p);
}

// ---------------- K_prep: fused split_a | split_b | v | wordp ----------------
#define PREP_BLOCKS 3648

__global__ void __launch_bounds__(256) k_prep(const float* __restrict__ img,
                                              const float* __restrict__ wf,
                                              const float* __restrict__ fc1w,
                                              const float* __restrict__ fc2w,
                                              const float* __restrict__ fc3w,
                                              const float* __restrict__ fc4w) {
    __shared__ float s[32 * 197];   // 25.2KB union
    int bx = blockIdx.x;
    int tid = threadIdx.x;

    if (bx < 256) {
        // ---- split_a: fp16 hi + fp16 residual ----
        int b = bx >> 6, c0 = (bx & 63) * 32;
        for (int e = tid; e < 32 * HW_; e += 256) {
            int ci = e / HW_, hw = e - ci * HW_;
            s[ci * 197 + hw] = img[((long)b * C_ + c0 + ci) * HW_ + hw];
        }
        __syncthreads();
        int ci = tid & 31, hw0 = tid >> 5;
        for (int hw = hw0; hw < HW_; hw += 8) {
            float x = s[ci * 197 + hw];
            __half h = __float2half_rn(x);
            __half l = __float2half_rn(x - __half2float(h));
            long o = (long)(b * HW_ + hw) * C_ + c0 + ci;
            g_ahi[o] = __half_as_ushort(h);
            g_alo[o] = __half_as_ushort(l);
        }
    } else if (bx < 2304) {
        // ---- split_b: fp16 of fc1_w (no residual) ----
        int idx = (bx - 256) * 256 + tid;    // float4 index
        float4 v = ((const float4*)fc1w)[idx];
        float vv[4] = {v.x, v.y, v.z, v.w};
        unsigned h[4];
#pragma unroll
        for (int i = 0; i < 4; i++)
            h[i] = __half_as_ushort(__float2half_rn(vv[i]));
        ((uint2*)g_bhi)[idx] = make_uint2(h[0] | (h[1] << 16), h[2] | (h[3] << 16));
    } else if (bx < 2368) {
        // ---- v ----
        int d0 = (bx - 2304) * 16;
        int dl = tid & 15, eg = tid >> 4;
        int d  = d0 + dl;
        float acc = 0.f;
        int e0 = eg * 64;
#pragma unroll 8
        for (int e = e0; e < e0 + 64; e++)
            acc = fmaf(fc4w[e], fc3w[e * ID + d], acc);
        s[tid] = acc;
        __syncthreads();
        if (tid < 16) {
            float sum = 0.f;
#pragma unroll
            for (int g = 0; g < 16; g++) sum += s[g * 16 + tid];
            g_v[d0 + tid] = sum;
        }
    } else {
        // ---- wordp: d-tile (8 rows of fc2w in smem) x n-group (8 n), warp-per-n
        int idx = bx - 2368;           // 0..1279
        int d0 = (idx & 127) * 8;
        int n  = (idx >> 7) * 8 + (tid >> 5);
        for (int e = tid; e < 8 * WD; e += 256) {
            int i = e / WD, k = e - i * WD;
            s[e] = fc2w[(long)(d0 + i) * WD + k];
        }
        __syncthreads();
        int lane = tid & 31;
        float acc[8] = {0, 0, 0, 0, 0, 0, 0, 0};
        const float* wrow = wf + n * WD;
        for (int k = lane; k < WD; k += 32) {
            float wv = wrow[k];
#pragma unroll
            for (int i = 0; i < 8; i++) acc[i] = fmaf(wv, s[i * WD + k], acc[i]);
        }
#pragma unroll
        for (int i = 0; i < 8; i++) {
#pragma unroll
            for (int off = 16; off; off >>= 1)
                acc[i] += __shfl_xor_sync(~0u, acc[i], off);
        }
        if (lane == 0) {
#pragma unroll
            for (int i = 0; i < 8; i++) g_wordp[n * ID + d0 + i] = acc[i];
        }
    }
}

// ---------------- K_mma: fp16 mma.sync, 2-term (ahi+alo)*bhi, 128x128, K-split 2 ----
// stage = Ahi[128x64B]=8KB | Alo 8KB | Bhi 8KB = 24KB; 4 stages = 96KB
#define AHI_OFF 0
#define ALO_OFF 8192
#define BHI_OFF 16384
#define STAGE_BYTES 24576
#define MMA_SMEM    (4 * STAGE_BYTES)   // 96KB dynamic
#define NCHUNK 32                       // K=1024 per CTA z-half, chunks of 32

__device__ __forceinline__ void cp16(uint32_t s, const void* g) {
    asm volatile("cp.async.cg.shared.global [%0], [%1], 16;" :: "r"(s), "l"(g));
}
__device__ __forceinline__ void ldm4(uint32_t* r, uint32_t a) {
    asm volatile("ldmatrix.sync.aligned.m8n8.x4.shared.b16 {%0,%1,%2,%3}, [%4];"
                 : "=r"(r[0]), "=r"(r[1]), "=r"(r[2]), "=r"(r[3]) : "r"(a));
}
__device__ __forceinline__ void mma16816(float* c, const uint32_t* a, uint32_t b0, uint32_t b1) {
    asm volatile("mma.sync.aligned.m16n8k16.row.col.f32.f16.f16.f32 "
                 "{%0,%1,%2,%3}, {%4,%5,%6,%7}, {%8,%9}, {%0,%1,%2,%3};"
                 : "+f"(c[0]), "+f"(c[1]), "+f"(c[2]), "+f"(c[3])
                 : "r"(a[0]), "r"(a[1]), "r"(a[2]), "r"(a[3]), "r"(b0), "r"(b1));
}
#define SWZ64(row, ch) ((uint32_t)((row) * 64 + (((ch) ^ (((row) >> 1) & 3)) << 4)))

__global__ void __launch_bounds__(256) k_mma() {
    extern __shared__ __align__(128) char smem[];
    uint32_t sbase = smem_u32(smem);
    int tid = threadIdx.x;
    int lane = tid & 31, wid = tid >> 5;
    int warp_m = wid >> 1, warp_n = wid & 1;        // 4 x 2 warps, warp 32M x 64N
    int m0 = blockIdx.y * 128, n0 = blockIdx.x * 128;
    long kz = (long)blockIdx.z * 1024;

    int lr = tid >> 2, c = tid & 3;
    uint32_t soff  = SWZ64(lr, c);
    uint32_t soff2 = SWZ64(lr + 64, c);
    long aGr  = (long)(m0 + lr) * C_ + kz + c * 8;
    long aGr2 = aGr + (long)64 * C_;
    long bGr  = (long)(n0 + lr) * C_ + kz + c * 8;
    long bGr2 = bGr + (long)64 * C_;

    auto load_stage = [&](int ci, int st) {
        uint32_t sa = sbase + (uint32_t)st * STAGE_BYTES;
        long ko = (long)ci * 32;
        cp16(sa + AHI_OFF + soff,  g_ahi + aGr  + ko);
        cp16(sa + AHI_OFF + soff2, g_ahi + aGr2 + ko);
        cp16(sa + ALO_OFF + soff,  g_alo + aGr  + ko);
        cp16(sa + ALO_OFF + soff2, g_alo + aGr2 + ko);
        cp16(sa + BHI_OFF + soff,  g_bhi + bGr  + ko);
        cp16(sa + BHI_OFF + soff2, g_bhi + bGr2 + ko);
        asm volatile("cp.async.commit_group;" ::: "memory");
    };

    int sel = lane >> 4;
    uint32_t a_off[2][2], b_off[4][2];
#pragma unroll
    for (int mt = 0; mt < 2; mt++) {
        int row = warp_m * 32 + mt * 16 + (lane & 15);
#pragma unroll
        for (int ks = 0; ks < 2; ks++)
            a_off[mt][ks] = SWZ64(row, 2 * ks + sel);
    }
#pragma unroll
    for (int bt = 0; bt < 4; bt++) {
        int row = warp_n * 64 + bt * 16 + (lane & 15);
#pragma unroll
        for (int ks = 0; ks < 2; ks++)
            b_off[bt][ks] = SWZ64(row, 2 * ks + sel);
    }

    float acc[2][8][4];
#pragma unroll
    for (int i = 0; i < 2; i++)
#pragma unroll
        for (int j = 0; j < 8; j++)
#pragma unroll
            for (int q = 0; q < 4; q++) acc[i][j][q] = 0.f;

    load_stage(0, 0);
    load_stage(1, 1);
    load_stage(2, 2);

    for (int ci = 0; ci < NCHUNK; ci++) {
        asm volatile("cp.async.wait_group 2;" ::: "memory");
        __syncthreads();
        if (ci + 3 < NCHUNK) load_stage(ci + 3, (ci + 3) & 3);
        else asm volatile("cp.async.commit_group;" ::: "memory");

        uint32_t sa = sbase + (uint32_t)(ci & 3) * STAGE_BYTES;
#pragma unroll
        for (int ks = 0; ks < 2; ks++) {
            uint32_t ahi[2][4], alo[2][4], bhi[4][4];
#pragma unroll
            for (int mt = 0; mt < 2; mt++) {
                ldm4(ahi[mt], sa + AHI_OFF + a_off[mt][ks]);
                ldm4(alo[mt], sa + ALO_OFF + a_off[mt][ks]);
            }
#pragma unroll
            for (int bt = 0; bt < 4; bt++)
                ldm4(bhi[bt], sa + BHI_OFF + b_off[bt][ks]);
#pragma unroll
            for (int mt = 0; mt < 2; mt++) {
#pragma unroll
                for (int bt = 0; bt < 4; bt++) {
                    mma16816(acc[mt][2 * bt],     ahi[mt], bhi[bt][0], bhi[bt][2]);
                    mma16816(acc[mt][2 * bt + 1], ahi[mt], bhi[bt][1], bhi[bt][3]);
                    mma16816(acc[mt][2 * bt],     alo[mt], bhi[bt][0], bhi[bt][2]);
                    mma16816(acc[mt][2 * bt + 1], alo[mt], bhi[bt][1], bhi[bt][3]);
                }
            }
        }
    }

    float* outb = blockIdx.z ? g_imgpB : g_imgpA;
#pragma unroll
    for (int mt = 0; mt < 2; mt++) {
#pragma unroll
        for (int nt = 0; nt < 8; nt++) {
            int prow = m0 + warp_m * 32 + mt * 16 + (lane >> 2);
            int ncol = n0 + warp_n * 64 + nt * 8 + (lane & 3) * 2;
            if (prow < M_)
                *(float2*)(outb + (long)prow * ID + ncol) =
                    make_float2(acc[mt][nt][0], acc[mt][nt][1]);
            if (prow + 8 < M_)
                *(float2*)(outb + (long)(prow + 8) * ID + ncol) =
                    make_float2(acc[mt][nt][2], acc[mt][nt][3]);
        }
    }
}

// ---------------- K_logits: 4 pixels x 40 classes per block (392 blocks) ----------------
__global__ void __launch_bounds__(256) k_logits() {
    __shared__ float s_img[4 * ID];
    __shared__ float s_v[ID];
    int p0 = (blockIdx.x >> 1) * 4;
    int n0 = (blockIdx.x & 1) * 40;
    for (int e = threadIdx.x; e < 4 * ID; e += 256) {
        long o = (long)p0 * ID + e;
        s_img[e] = g_imgpA[o] + g_imgpB[o];
    }
    for (int e = threadIdx.x; e < ID; e += 256) s_v[e] = g_v[e];
    __syncthreads();
    int w = threadIdx.x >> 5, lane = threadIdx.x & 31;
    int b = p0 / HW_;                  // 4 | 196 so no straddle
    int hw0 = p0 - b * HW_;
    for (int n = n0 + w; n < n0 + 40; n += 8) {
        const float* wrow = g_wordp + n * ID;
        float a0 = 0.f, a1 = 0.f, a2 = 0.f, a3 = 0.f;
#pragma unroll 4
        for (int d = lane; d < ID; d += 32) {
            float wv = wrow[d];
            float vv = s_v[d];
            float t0, t1, t2, t3;
            float x0 = s_img[d] * wv;
            float x1 = s_img[ID + d] * wv;
            float x2 = s_img[2 * ID + d] * wv;
            float x3 = s_img[3 * ID + d] * wv;
            asm("tanh.approx.f32 %0, %1;" : "=f"(t0) : "f"(x0));
            asm("tanh.approx.f32 %0, %1;" : "=f"(t1) : "f"(x1));
            asm("tanh.approx.f32 %0, %1;" : "=f"(t2) : "f"(x2));
            asm("tanh.approx.f32 %0, %1;" : "=f"(t3) : "f"(x3));
            a0 = fmaf(vv, t0, a0);
            a1 = fmaf(vv, t1, a1);
            a2 = fmaf(vv, t2, a2);
            a3 = fmaf(vv, t3, a3);
        }
#pragma unroll
        for (int off = 16; off; off >>= 1) {
            a0 += __shfl_xor_sync(~0u, a0, off);
            a1 += __shfl_xor_sync(~0u, a1, off);
            a2 += __shfl_xor_sync(~0u, a2, off);
            a3 += __shfl_xor_sync(~0u, a3, off);
        }
        if (lane == 0) {
            float* dst = g_logits + (b * NCLS + n) * HW_ + hw0;
            dst[0] = a0; dst[1] = a1; dst[2] = a2; dst[3] = a3;
        }
    }
}

// ---------------- K_softmax: warp-per-(b,n) row over 196 positions ----------------
__global__ void __launch_bounds__(256) k_softmax() {
    int row = blockIdx.x * 8 + (threadIdx.x >> 5);   // 40 blocks x 8 warps = 320 rows
    float* base = g_logits + row * HW_;
    int lane = threadIdx.x & 31;
    float v[7];
    float mx = -1e30f;
#pragma unroll
    for (int i = 0; i < 7; i++) {
        int hw = lane + 32 * i;
        v[i] = (hw < HW_) ? base[hw] : -1e30f;
        mx = fmaxf(mx, v[i]);
    }
#pragma unroll
    for (int off = 16; off; off >>= 1) mx = fmaxf(mx, __shfl_xor_sync(~0u, mx, off));
    float sum = 0.f;
#pragma unroll
    for (int i = 0; i < 7; i++) {
        int hw = lane + 32 * i;
        float e = (hw < HW_) ? __expf(v[i] - mx) : 0.0f;
        v[i] = e;
        sum += e;
    }
#pragma unroll
    for (int off = 16; off; off >>= 1) sum += __shfl_xor_sync(~0u, sum, off);
    float inv = __fdividef(1.0f, sum);
#pragma unroll
    for (int i = 0; i < 7; i++) {
        int hw = lane + 32 * i;
        if (hw < HW_) base[hw] = v[i] * inv;
    }
}

// ---------------- K_pool: out[b,n,c] = sum_hw coef[b,n,hw] * x[b,hw,c] ----------------
// block = (32 c, 40 n, b); grid (64,2,4) = 512 blocks; float4 fills + inner loop
#define HW4 (HW_ / 4)                              // 49
#define POOL_SMEM ((32 * HW_ + 40 * HW_) * 4)      // 56448 B

__global__ void __launch_bounds__(256) k_pool(const float* __restrict__ img,
                                              float* __restrict__ out) {
    extern __shared__ __align__(16) float sp[];
    float* s_x = sp;                 // [32][196]
    float* s_c = sp + 32 * HW_;      // [40][196]
    int b  = blockIdx.z;
    int nh = blockIdx.y;             // n-half: classes [nh*40, nh*40+40)
    int c0 = blockIdx.x * 32;
    int tid = threadIdx.x;

    const float4* imgB = (const float4*)(img + (long)b * C_ * HW_);
    float4* sx4 = (float4*)s_x;
    for (int e = tid; e < 32 * HW4; e += 256) {
        int cl = e / HW4, q = e - cl * HW4;
        sx4[e] = imgB[(long)(c0 + cl) * HW4 + q];
    }
    const float4* log4 = (const float4*)(g_logits + ((long)b * NCLS + nh * 40) * HW_);
    float4* sc4 = (float4*)s_c;
    for (int e = tid; e < 40 * HW4; e += 256)
        sc4[e] = log4[e];
    __syncthreads();

    int cl = tid & 31, np = tid >> 5;   // warp np handles local n = np + 8j, j<5
    float acc[5];
#pragma unroll
    for (int j = 0; j < 5; j++) acc[j] = 0.f;

    const float4* x4 = (const float4*)(s_x + cl * HW_);
    for (int q = 0; q < HW4; q++) {
        float4 xv = x4[q];
#pragma unroll
        for (int j = 0; j < 5; j++) {
            float4 cv = *(const float4*)(s_c + (np + 8 * j) * HW_ + 4 * q);
            acc[j] = fmaf(xv.x, cv.x, acc[j]);
            acc[j] = fmaf(xv.y, cv.y, acc[j]);
            acc[j] = fmaf(xv.z, cv.z, acc[j]);
            acc[j] = fmaf(xv.w, cv.w, acc[j]);
        }
    }
#pragma unroll
    for (int j = 0; j < 5; j++) {
        int n = nh * 40 + np + 8 * j;
        out[((long)b * NCLS + n) * C_ + c0 + cl] = acc[j];
    }
}

// ---------------- launch ----------------
extern "C" void kernel_launch(void* const* d_in, const int* in_sizes, int n_in,
                              void* d_out, int out_size) {
    (void)in_sizes; (void)n_in; (void)out_size;
    const float* img  = (const float*)d_in[0];  // [B,C,H,W]
    const float* wf   = (const float*)d_in[1];  // [N,WD]
    const float* fc1w = (const float*)d_in[2];  // [ID,C]
    const float* fc2w = (const float*)d_in[3];  // [ID,WD]
    const float* fc3w = (const float*)d_in[4];  // [ID,ID]
    // d_in[5] fc3_b, d_in[7] fc4_b: constant over softmax axis -> cancel
    const float* fc4w = (const float*)d_in[6];  // [1,ID]
    float* out = (float*)d_out;                 // [B,N,C] fp32

    cudaFuncSetAttribute(k_mma,  cudaFuncAttributeMaxDynamicSharedMemorySize, MMA_SMEM);
    cudaFuncSetAttribute(k_pool, cudaFuncAttributeMaxDynamicSharedMemorySize, POOL_SMEM);

    k_prep   <<<PREP_BLOCKS, 256>>>(img, wf, fc1w, fc2w, fc3w, fc4w);
    k_mma    <<<dim3(8, 7, 2), 256, MMA_SMEM>>>();
    k_logits <<<392, 256>>>();
    k_softmax<<<40, 256>>>();
    k_pool   <<<dim3(64, 2, 4), 256, POOL_SMEM>>>(img, out);
}